// round 2
// baseline (speedup 1.0000x reference)
#include <cuda_runtime.h>

// Shapes are fixed by the problem: N=8192, D=64.
#define N_ROWS 8192
#define D_DIM  64

// Scratch for GEMV results (no cudaMalloc allowed).
__device__ float g_s1[N_ROWS];
__device__ float g_s2[N_ROWS];

// Kernel 1: s1 = Wh @ a[:64], s2 = Wh @ a[64:128].
// One warp per row; each lane owns a float2 (64 elems / 32 lanes).
__global__ void gemv_kernel(const float* __restrict__ Wh,
                            const float* __restrict__ a) {
    const int warps_per_block = blockDim.x >> 5;
    const int row  = blockIdx.x * warps_per_block + (threadIdx.x >> 5);
    const int lane = threadIdx.x & 31;
    if (row >= N_ROWS) return;

    const float2 w  = reinterpret_cast<const float2*>(Wh + (size_t)row * D_DIM)[lane];
    const float2 a1 = reinterpret_cast<const float2*>(a)[lane];
    const float2 a2 = reinterpret_cast<const float2*>(a + D_DIM)[lane];

    float s1 = w.x * a1.x + w.y * a1.y;
    float s2 = w.x * a2.x + w.y * a2.y;

    #pragma unroll
    for (int off = 16; off > 0; off >>= 1) {
        s1 += __shfl_xor_sync(0xFFFFFFFFu, s1, off);
        s2 += __shfl_xor_sync(0xFFFFFFFFu, s2, off);
    }
    if (lane == 0) {
        g_s1[row] = s1;
        g_s2[row] = s2;
    }
}

__device__ __forceinline__ float leaky(float e) {
    // e >= 0 ? e : 0.2*e  ==  max(e, 0.2*e) for all e
    return fmaxf(e, 0.2f * e);
}

// Kernel 2: out[i][j] = leaky(s1[i] + s2[j]); one thread per float4.
// 8192 rows x 2048 float4-cols. Streaming stores (evict-first) to keep
// the 256MB write stream from thrashing L2.
__global__ void outer_kernel(float4* __restrict__ out) {
    const int row = blockIdx.y;
    const int c4  = blockIdx.x * blockDim.x + threadIdx.x;   // 0..2047

    const float  s1 = g_s1[row];
    const float4 s2 = reinterpret_cast<const float4*>(g_s2)[c4];

    float4 e;
    e.x = leaky(s1 + s2.x);
    e.y = leaky(s1 + s2.y);
    e.z = leaky(s1 + s2.z);
    e.w = leaky(s1 + s2.w);

    __stcs(&out[(size_t)row * (N_ROWS / 4) + c4], e);
}

extern "C" void kernel_launch(void* const* d_in, const int* in_sizes, int n_in,
                              void* d_out, int out_size) {
    const float* Wh = (const float*)d_in[0];
    const float* a  = (const float*)d_in[1];
    float4* out = (float4*)d_out;

    // Kernel 1: 8192 warps -> 8 warps/block, 1024 blocks
    gemv_kernel<<<N_ROWS / 8, 256>>>(Wh, a);

    // Kernel 2: 2048 float4 per row -> 8 blocks of 256 threads per row
    dim3 grid(N_ROWS / 4 / 256, N_ROWS);
    outer_kernel<<<grid, 256>>>(out);
}